// round 1
// baseline (speedup 1.0000x reference)
#include <cuda_runtime.h>
#include <math.h>

#define NN   50000
#define EE   800000
#define KDIM 128
#define HH   8
#define CC   16
#define EDIMC 16
#define OUTC 64

// ------------------------- device scratch (no allocs allowed) ----------------
__device__ float g_xl[NN * KDIM];
__device__ float g_xr[NN * KDIM];
__device__ float g_h [NN * KDIM];
__device__ int   g_deg[NN];
__device__ int   g_off[NN];
__device__ int   g_cur[NN];
__device__ int   g_eid[EE];
__device__ int   g_bsum[64];
__device__ int   g_boff[64];

// ------------------------- f32x2 helpers (Blackwell packed fp32) -------------
__device__ __forceinline__ unsigned long long pack2(float a, float b) {
    unsigned long long r;
    asm("mov.b64 %0, {%1, %2};" : "=l"(r) : "f"(a), "f"(b));
    return r;
}
__device__ __forceinline__ unsigned long long fma2(unsigned long long a,
                                                   unsigned long long b,
                                                   unsigned long long c) {
    unsigned long long d;
    asm("fma.rn.f32x2 %0, %1, %2, %3;" : "=l"(d) : "l"(a), "l"(b), "l"(c));
    return d;
}
__device__ __forceinline__ void unpack2(unsigned long long v, float& a, float& b) {
    asm("mov.b64 {%0, %1}, %2;" : "=f"(a), "=f"(b) : "l"(v));
}

// ------------------------- CSR build -----------------------------------------
__global__ void k_zero_deg() {
    int i = blockIdx.x * 256 + threadIdx.x;
    if (i < NN) g_deg[i] = 0;
}

__global__ void k_hist(const int* __restrict__ dst) {
    int e = blockIdx.x * 256 + threadIdx.x;
    if (e < EE) atomicAdd(&g_deg[dst[e]], 1);
}

__global__ __launch_bounds__(1024) void k_scan1() {
    __shared__ int wsum[32];
    int t = threadIdx.x;
    int i = blockIdx.x * 1024 + t;
    int v = (i < NN) ? g_deg[i] : 0;
    int x = v;
#pragma unroll
    for (int o = 1; o < 32; o <<= 1) {
        int y = __shfl_up_sync(0xffffffffu, x, o);
        if ((t & 31) >= o) x += y;
    }
    if ((t & 31) == 31) wsum[t >> 5] = x;
    __syncthreads();
    if (t < 32) {
        int s = wsum[t];
#pragma unroll
        for (int o = 1; o < 32; o <<= 1) {
            int y = __shfl_up_sync(0xffffffffu, s, o);
            if (t >= o) s += y;
        }
        wsum[t] = s;
    }
    __syncthreads();
    int base = (t >= 32) ? wsum[(t >> 5) - 1] : 0;
    int incl = x + base;
    if (i < NN) g_off[i] = incl - v;   // exclusive within block
    if (t == 1023) g_bsum[blockIdx.x] = incl;
}

__global__ void k_scan2(int nb) {
    if (threadIdx.x == 0) {
        int run = 0;
        for (int i = 0; i < nb; i++) { g_boff[i] = run; run += g_bsum[i]; }
    }
}

__global__ void k_fixup() {
    int i = blockIdx.x * 256 + threadIdx.x;
    if (i < NN) {
        int o = g_off[i] + g_boff[i / 1024];
        g_off[i] = o;
        g_cur[i] = o;
    }
}

__global__ void k_scatter(const int* __restrict__ dst) {
    int e = blockIdx.x * 256 + threadIdx.x;
    if (e < EE) {
        int d = dst[e];
        int p = atomicAdd(&g_cur[d], 1);
        g_eid[p] = e;
    }
}

// deterministic edge order within each node (insertion sort, avg degree 16)
__global__ void k_sort() {
    int v = blockIdx.x * 256 + threadIdx.x;
    if (v >= NN) return;
    int st = g_off[v], n = g_deg[v];
    for (int i = 1; i < n; i++) {
        int key = g_eid[st + i];
        int j = i - 1;
        while (j >= 0 && g_eid[st + j] > key) {
            g_eid[st + j + 1] = g_eid[st + j];
            j--;
        }
        g_eid[st + j + 1] = key;
    }
}

// ------------------------- block GEMM: Y[n,NCOLS] = X[n,128] @ W + b ---------
// 64 rows / block, W fully smem-resident, f32x2 packed math.
#define XS_STRIDE 132

template <int NCOLS>
__global__ __launch_bounds__(256) void gemm_kernel(
    const float* __restrict__ X, const float* __restrict__ W,
    const float* __restrict__ bias, float* __restrict__ Y, int nrows)
{
    constexpr int CT  = NCOLS / 16;   // col thread-groups (16 cols per thread)
    constexpr int RT  = 256 / CT;     // row threads
    constexpr int RPT = 64 / RT;      // rows per thread
    extern __shared__ float sm[];
    float* ws = sm;                      // [128 * NCOLS]
    float* xs = sm + 128 * NCOLS;        // [64 * XS_STRIDE]
    int tid  = threadIdx.x;
    int row0 = blockIdx.x * 64;

    {   // load W
        const float4* w4 = (const float4*)W;
        float4* s4 = (float4*)ws;
        constexpr int WT = 128 * NCOLS / 4;
#pragma unroll
        for (int i = tid; i < WT; i += 256) s4[i] = w4[i];
    }
    {   // load X tile (padded rows, zero tail)
        const float4* x4 = (const float4*)X;
        float4* s4 = (float4*)xs;
#pragma unroll
        for (int i = tid; i < 64 * 32; i += 256) {
            int r = i >> 5, c4 = i & 31;
            int gr = row0 + r;
            float4 val = (gr < nrows) ? x4[(size_t)gr * 32 + c4]
                                      : make_float4(0.f, 0.f, 0.f, 0.f);
            s4[r * (XS_STRIDE / 4) + c4] = val;
        }
    }
    __syncthreads();

    int ct = tid % CT, rt = tid / CT;
    int c0 = ct * 16;
    int rb = rt * RPT;

    unsigned long long acc[RPT][8];
#pragma unroll
    for (int i = 0; i < RPT; i++)
#pragma unroll
        for (int j = 0; j < 8; j++) acc[i][j] = 0ull;

#pragma unroll 4
    for (int k = 0; k < 128; k++) {
        unsigned long long w[8];
#pragma unroll
        for (int j = 0; j < 8; j++)
            w[j] = *(const unsigned long long*)&ws[k * NCOLS + c0 + 2 * j];
#pragma unroll
        for (int i = 0; i < RPT; i++) {
            float xv = xs[(rb + i) * XS_STRIDE + k];
            unsigned long long x2 = pack2(xv, xv);
#pragma unroll
            for (int j = 0; j < 8; j++) acc[i][j] = fma2(x2, w[j], acc[i][j]);
        }
    }

    float bl[16];
#pragma unroll
    for (int j = 0; j < 16; j++) bl[j] = bias[c0 + j];

#pragma unroll
    for (int i = 0; i < RPT; i++) {
        int gr = row0 + rb + i;
        if (gr < nrows) {
            float o[16];
#pragma unroll
            for (int j = 0; j < 8; j++) unpack2(acc[i][j], o[2 * j], o[2 * j + 1]);
#pragma unroll
            for (int j = 0; j < 16; j++) o[j] += bl[j];
            float4* yp = (float4*)(Y + (size_t)gr * NCOLS + c0);
#pragma unroll
            for (int q = 0; q < 4; q++)
                yp[q] = make_float4(o[4 * q], o[4 * q + 1], o[4 * q + 2], o[4 * q + 3]);
        }
    }
}

// ------------------------- fused GATv2 aggregation ---------------------------
// warp per destination node; lane owns 4 channels (head = lane/4).
// computes edge embedding + leaky_relu + logits + softmax-weighted sum of
// xl[src], then divide + bias + ELU, all in one pass. No atomics.
__global__ __launch_bounds__(256) void k_agg(
    const float* __restrict__ xl, const float* __restrict__ xr,
    const int*   __restrict__ src_arr, const float* __restrict__ ea,
    const float* __restrict__ We, const float* __restrict__ att,
    const float* __restrict__ bias, float* __restrict__ out)
{
    __shared__ float sWe[EDIMC * KDIM];   // 8 KB
    __shared__ float sAtt[KDIM];
    int tid = threadIdx.x;
    {
        const float4* w4 = (const float4*)We;
        float4* s4 = (float4*)sWe;
        s4[tid]       = w4[tid];
        s4[tid + 256] = w4[tid + 256];
    }
    if (tid < 128) sAtt[tid] = att[tid];
    __syncthreads();

    int warp = tid >> 5, lane = tid & 31;
    int v = blockIdx.x * 8 + warp;
    if (v >= NN) return;
    int c0 = lane * 4;

    // register-resident We slice (16 k x 4 cols as 2 f32x2 pairs)
    unsigned long long wreg[EDIMC][2];
#pragma unroll
    for (int k = 0; k < EDIMC; k++) {
        wreg[k][0] = *(const unsigned long long*)&sWe[k * KDIM + c0];
        wreg[k][1] = *(const unsigned long long*)&sWe[k * KDIM + c0 + 2];
    }
    float attv[4];
#pragma unroll
    for (int j = 0; j < 4; j++) attv[j] = sAtt[c0 + j];

    float4 xr4 = *(const float4*)(xr + (size_t)v * KDIM + c0);

    float acc0 = 0.f, acc1 = 0.f, acc2 = 0.f, acc3 = 0.f, den = 0.f;
    int st = g_off[v], dg = g_deg[v];

    int e_cur = 0, s_cur = 0;
    if (dg > 0) { e_cur = g_eid[st]; s_cur = src_arr[e_cur]; }

    for (int i = 0; i < dg; i++) {
        int e_nxt = e_cur, s_nxt = s_cur;
        if (i + 1 < dg) { e_nxt = g_eid[st + i + 1]; s_nxt = src_arr[e_nxt]; }

        const float4* eap = (const float4*)(ea + (size_t)e_cur * EDIMC);
        float4 ea0 = eap[0], ea1 = eap[1], ea2 = eap[2], ea3 = eap[3];
        float4 xl4 = *(const float4*)(xl + (size_t)s_cur * KDIM + c0);

        float eav[16] = {ea0.x, ea0.y, ea0.z, ea0.w, ea1.x, ea1.y, ea1.z, ea1.w,
                         ea2.x, ea2.y, ea2.z, ea2.w, ea3.x, ea3.y, ea3.z, ea3.w};
        unsigned long long p0 = 0ull, p1 = 0ull;
#pragma unroll
        for (int k = 0; k < EDIMC; k++) {
            unsigned long long a2 = pack2(eav[k], eav[k]);
            p0 = fma2(a2, wreg[k][0], p0);
            p1 = fma2(a2, wreg[k][1], p1);
        }
        float ee0, ee1, ee2, ee3;
        unpack2(p0, ee0, ee1);
        unpack2(p1, ee2, ee3);

        float m0 = xl4.x + xr4.x + ee0; m0 = fmaxf(m0, 0.2f * m0);
        float m1 = xl4.y + xr4.y + ee1; m1 = fmaxf(m1, 0.2f * m1);
        float m2 = xl4.z + xr4.z + ee2; m2 = fmaxf(m2, 0.2f * m2);
        float m3 = xl4.w + xr4.w + ee3; m3 = fmaxf(m3, 0.2f * m3);

        float lg = m0 * attv[0];
        lg = fmaf(m1, attv[1], lg);
        lg = fmaf(m2, attv[2], lg);
        lg = fmaf(m3, attv[3], lg);
        // reduce over the 4 lanes of this head
        lg += __shfl_xor_sync(0xffffffffu, lg, 1);
        lg += __shfl_xor_sync(0xffffffffu, lg, 2);

        float ex = __expf(lg);   // max-shift skipped: alpha ratio is invariant
        acc0 = fmaf(ex, xl4.x, acc0);
        acc1 = fmaf(ex, xl4.y, acc1);
        acc2 = fmaf(ex, xl4.z, acc2);
        acc3 = fmaf(ex, xl4.w, acc3);
        den += ex;

        e_cur = e_nxt; s_cur = s_nxt;
    }

    float inv = 1.0f / (den + 1e-16f);
    float o0 = acc0 * inv + bias[c0 + 0];
    float o1 = acc1 * inv + bias[c0 + 1];
    float o2 = acc2 * inv + bias[c0 + 2];
    float o3 = acc3 * inv + bias[c0 + 3];
    o0 = (o0 > 0.f) ? o0 : expm1f(o0);
    o1 = (o1 > 0.f) ? o1 : expm1f(o1);
    o2 = (o2 > 0.f) ? o2 : expm1f(o2);
    o3 = (o3 > 0.f) ? o3 : expm1f(o3);
    *(float4*)(out + (size_t)v * KDIM + c0) = make_float4(o0, o1, o2, o3);
}

// ------------------------- launch --------------------------------------------
extern "C" void kernel_launch(void* const* d_in, const int* in_sizes, int n_in,
                              void* d_out, int out_size)
{
    const float* x    = (const float*)d_in[0];
    const int*   ei   = (const int*)  d_in[1];
    const float* ea   = (const float*)d_in[2];
    const float* Wl1  = (const float*)d_in[3];
    const float* bl1  = (const float*)d_in[4];
    const float* Wr1  = (const float*)d_in[5];
    const float* br1  = (const float*)d_in[6];
    const float* We1  = (const float*)d_in[7];
    const float* att1 = (const float*)d_in[8];
    const float* b1   = (const float*)d_in[9];
    const float* Wl2  = (const float*)d_in[10];
    const float* bl2  = (const float*)d_in[11];
    const float* Wr2  = (const float*)d_in[12];
    const float* br2  = (const float*)d_in[13];
    const float* We2  = (const float*)d_in[14];
    const float* att2 = (const float*)d_in[15];
    const float* b2   = (const float*)d_in[16];
    const float* Wc   = (const float*)d_in[17];
    const float* bc   = (const float*)d_in[18];

    float *xl, *xr, *hbuf;
    cudaGetSymbolAddress((void**)&xl,   g_xl);
    cudaGetSymbolAddress((void**)&xr,   g_xr);
    cudaGetSymbolAddress((void**)&hbuf, g_h);

    const int* srcp = ei;
    const int* dstp = ei + EE;

    const int SMEM128 = (128 * 128 + 64 * XS_STRIDE) * 4;   // 99328 B
    const int SMEM64  = (128 * 64  + 64 * XS_STRIDE) * 4;   // 66560 B
    cudaFuncSetAttribute((const void*)gemm_kernel<128>,
                         cudaFuncAttributeMaxDynamicSharedMemorySize, SMEM128);
    cudaFuncSetAttribute((const void*)gemm_kernel<64>,
                         cudaFuncAttributeMaxDynamicSharedMemorySize, SMEM64);

    // ---- CSR build (shared by both layers) ----
    k_zero_deg<<<(NN + 255) / 256, 256>>>();
    k_hist<<<(EE + 255) / 256, 256>>>(dstp);
    k_scan1<<<(NN + 1023) / 1024, 1024>>>();
    k_scan2<<<1, 32>>>((NN + 1023) / 1024);
    k_fixup<<<(NN + 255) / 256, 256>>>();
    k_scatter<<<(EE + 255) / 256, 256>>>(dstp);
    k_sort<<<(NN + 255) / 256, 256>>>();

    dim3 ggrid((NN + 63) / 64);
    dim3 agrid((NN + 7) / 8);

    // ---- layer 1 ----
    gemm_kernel<128><<<ggrid, 256, SMEM128>>>(x, Wl1, bl1, xl, NN);
    gemm_kernel<128><<<ggrid, 256, SMEM128>>>(x, Wr1, br1, xr, NN);
    k_agg<<<agrid, 256>>>(xl, xr, srcp, ea, We1, att1, b1, hbuf);

    // ---- layer 2 ----
    gemm_kernel<128><<<ggrid, 256, SMEM128>>>(hbuf, Wl2, bl2, xl, NN);
    gemm_kernel<128><<<ggrid, 256, SMEM128>>>(hbuf, Wr2, br2, xr, NN);
    k_agg<<<agrid, 256>>>(xl, xr, srcp, ea, We2, att2, b2, hbuf);

    // ---- classifier ----
    gemm_kernel<64><<<ggrid, 256, SMEM64>>>(hbuf, Wc, bc, (float*)d_out, NN);
}